// round 4
// baseline (speedup 1.0000x reference)
#include <cuda_runtime.h>

#define NTOT 12544   // 16 * 784 flattened spatial*batch
#define HWSZ 784
#define WD   28

// ---------------- scratch (device globals; no allocation allowed) ----------
__device__ float g_xT  [512 * NTOT];   // x transposed to [c][n]
__device__ float g_A   [512 * NTOT];   // t1 (128 rows) then t3 (512 rows)
__device__ float g_B   [128 * NTOT];   // u1 then u2
__device__ float g_C   [128 * NTOT];   // t2
__device__ float g_q1T [512 * 128];    // quantized w1s, k-major [c][p]
__device__ float g_w1aT[128 * 128];    // w1a k-major, NEGATED
__device__ float g_q2T [1152 * 128];
__device__ float g_w2aT[1152 * 128];   // negated
__device__ float g_q3T [128 * 512];
__device__ float g_w3aT[512 * 512];    // negated

template<int ID>
__device__ __forceinline__ float* gbuf(float* rt) {
    if constexpr (ID == 0) return g_xT;
    else if constexpr (ID == 1) return g_A;
    else if constexpr (ID == 2) return g_B;
    else if constexpr (ID == 3) return g_C;
    else if constexpr (ID == 4) return g_q1T;
    else if constexpr (ID == 5) return g_w1aT;
    else if constexpr (ID == 6) return g_q2T;
    else if constexpr (ID == 7) return g_w2aT;
    else if constexpr (ID == 8) return g_q3T;
    else if constexpr (ID == 9) return g_w3aT;
    else return rt;
}

// ---- one kernel for all weight prep (quantize/negate + k-major transpose) -
__device__ __forceinline__ void wp_one(const float* src, float* dst,
                                       int i, int M, int K, int quant, int neg) {
    int m = i / K, k = i - m * K;
    float w = src[i];
    float q = w;
    if (quant) {
        float a = fabsf(w) + 1e-8f;
        q = copysignf(exp2f(rintf(log2f(a))), w);
        if (w == 0.0f) q = 0.0f;   // jnp.sign(0) == 0
    }
    if (neg) q = -q;
    dst[k * M + m] = q;
}

__global__ void wprep_all(const float* __restrict__ w1s, const float* __restrict__ w1a,
                          const float* __restrict__ w2s, const float* __restrict__ w2a,
                          const float* __restrict__ w3s, const float* __restrict__ w3a) {
    int gid = blockIdx.x * blockDim.x + threadIdx.x;
    // segment offsets: sizes 65536,16384,147456,147456,65536,262144
    if (gid < 65536)                 wp_one(w1s, g_q1T,  gid,          128, 512,  1, 0);
    else if (gid < 81920)            wp_one(w1a, g_w1aT, gid - 65536,  128, 128,  0, 1);
    else if (gid < 229376)           wp_one(w2s, g_q2T,  gid - 81920,  128, 1152, 1, 0);
    else if (gid < 376832)           wp_one(w2a, g_w2aT, gid - 229376, 128, 1152, 0, 1);
    else if (gid < 442368)           wp_one(w3s, g_q3T,  gid - 376832, 512, 128,  1, 0);
    else if (gid < 704512)           wp_one(w3a, g_w3aT, gid - 442368, 512, 512,  0, 1);
}

// -------- x: NCHW -> [c][b*784+hw] ----------------------------------------
__global__ void transpose_x(const float* __restrict__ x) {
    int i = blockIdx.x * blockDim.x + threadIdx.x;   // float4 index
    if (i >= 512 * (NTOT / 4)) return;
    int c  = i / (NTOT / 4);
    int r  = i - c * (NTOT / 4);
    int n  = r * 4;
    int b  = n / HWSZ;
    int hw = n - b * HWSZ;
    float4 v = ((const float4*)x)[((b * 512 + c) * HWSZ + hw) >> 2];
    ((float4*)g_xT)[i] = v;
}

// ---------------------------------------------------------------------------
// GEMM-shaped kernel. BN=128, 256 threads, TM x 8 thread tile,
// A tile stored DUPLICATED in smem ([a,a,...]) so LDS.128 yields ready
// {a,a} 64-bit operands — zero pack MOVs in the inner loop.
//   MODE 0: acc += a*b   MODE 1: acc += |b-a| (A negated; epilogue negates)
//   CONV 0: B = X[k][n]  CONV 1: implicit 3x3, zero halo (BK=18)
//   EPI 0: plain  EPI 1: relu(bn)  EPI 2: relu(bn+resid) NCHW store
// ---------------------------------------------------------------------------
template<int BM, int TM, int BK, int MODE, int CONV, int EPI,
         int WID, int XID, int YID>
__global__ void __launch_bounds__(256)
gx(float* Yrt, int Mtot, int K,
   const float* __restrict__ bg, const float* __restrict__ bb,
   const float* __restrict__ bm, const float* __restrict__ bv,
   const float* __restrict__ resid)
{
    constexpr int BN = 128, NT = 256;
    static_assert((BM / TM) * (BN / 8) == NT, "bad tile");
    constexpr int AF4 = BK * BM / 4;
    constexpr int AU  = (AF4 + NT - 1) / NT;
    const float* Wt = gbuf<WID>(nullptr);
    const float* X  = gbuf<XID>(nullptr);
    float*       Y  = gbuf<YID>(Yrt);

    __shared__ __align__(16) float As[2][BK * BM * 2];   // duplicated
    __shared__ __align__(16) float Bs[2][BK * BN];

    int tid = threadIdx.x;
    int tx  = tid % 16;            // 16 col groups of 8
    int ty  = tid / 16;            // row groups of TM
    int m0  = blockIdx.y * BM;
    int n0  = blockIdx.x * BN;

    // conv geometry: thread owns column (tid&127), tid>>7 picks channel half
    int ccol = tid & 127, chalf = tid >> 7;
    int cn = n0 + ccol;
    int cw = cn % WD;
    int ch = (cn / WD) % WD;

    float4 pa[AU];
    float4 pb[2];
    float  pc[9];

    auto loadA = [&](int k0) {
#pragma unroll
        for (int u = 0; u < AU; u++) {
            int v = tid + u * NT;
            if (AF4 % NT == 0 || v < AF4) {
                int kk = v / (BM / 4), mq = v - kk * (BM / 4);
                pa[u] = *(const float4*)&Wt[(k0 + kk) * Mtot + m0 + mq * 4];
            }
        }
    };
    auto storeA = [&](int buf) {
#pragma unroll
        for (int u = 0; u < AU; u++) {
            int v = tid + u * NT;
            if (AF4 % NT == 0 || v < AF4) {
                int kk = v / (BM / 4), mq = v - kk * (BM / 4);
                float* d = &As[buf][kk * BM * 2 + mq * 8];
                *(float4*)(d)     = make_float4(pa[u].x, pa[u].x, pa[u].y, pa[u].y);
                *(float4*)(d + 4) = make_float4(pa[u].z, pa[u].z, pa[u].w, pa[u].w);
            }
        }
    };
    auto loadB = [&](int k0) {
        if (CONV == 0) {
#pragma unroll
            for (int u = 0; u < BK * BN / 4 / NT; u++) {
                int v = tid + u * NT;
                int kk = v / (BN / 4), nq = v - kk * (BN / 4);
                pb[u] = *(const float4*)&X[(k0 + kk) * NTOT + n0 + nq * 4];
            }
        } else {
            int c = k0 / 9 + chalf;
#pragma unroll
            for (int q = 0; q < 9; q++) {
                const int r = q / 3, s = q % 3;
                int hh = ch + r - 1, ww = cw + s - 1;
                float val = 0.0f;
                if (hh >= 0 && hh < WD && ww >= 0 && ww < WD)
                    val = X[c * NTOT + cn + (r - 1) * WD + (s - 1)];
                pc[q] = val;
            }
        }
    };
    auto storeB = [&](int buf) {
        if (CONV == 0) {
#pragma unroll
            for (int u = 0; u < BK * BN / 4 / NT; u++) {
                int v = tid + u * NT;
                int kk = v / (BN / 4), nq = v - kk * (BN / 4);
                *(float4*)&Bs[buf][kk * BN + nq * 4] = pb[u];
            }
        } else {
#pragma unroll
            for (int q = 0; q < 9; q++)
                Bs[buf][(chalf * 9 + q) * BN + ccol] = pc[q];
        }
    };

    unsigned long long acc2[TM][4];
#pragma unroll
    for (int i = 0; i < TM; i++)
#pragma unroll
        for (int j = 0; j < 4; j++) acc2[i][j] = 0ULL;

    loadA(0); loadB(0);
    storeA(0); storeB(0);
    __syncthreads();

    int T = K / BK;
    for (int t = 0; t < T; t++) {
        int buf = t & 1;
        if (t + 1 < T) { loadA((t + 1) * BK); loadB((t + 1) * BK); }

#pragma unroll
        for (int kk = 0; kk < BK; kk++) {
            // a dups: TM/2 LDS.128, each = two ready {a,a} pairs
            unsigned long long ad[TM];
#pragma unroll
            for (int h = 0; h < TM / 2; h++) {
                ulonglong2 p = *(const ulonglong2*)
                    &As[buf][kk * BM * 2 + ty * TM * 2 + h * 4];
                ad[2 * h] = p.x; ad[2 * h + 1] = p.y;
            }
            // b pairs: 2 LDS.128 = four 64-bit {b,b'} pairs
            unsigned long long b2[4];
            {
                ulonglong2 p0 = *(const ulonglong2*)&Bs[buf][kk * BN + tx * 8];
                ulonglong2 p1 = *(const ulonglong2*)&Bs[buf][kk * BN + tx * 8 + 4];
                b2[0] = p0.x; b2[1] = p0.y; b2[2] = p1.x; b2[3] = p1.y;
            }
#pragma unroll
            for (int i = 0; i < TM; i++)
#pragma unroll
                for (int jp = 0; jp < 4; jp++) {
                    if (MODE == 0) {
                        asm("fma.rn.f32x2 %0, %1, %2, %0;"
                            : "+l"(acc2[i][jp]) : "l"(ad[i]), "l"(b2[jp]));
                    } else {
                        unsigned long long d;
                        asm("add.rn.f32x2 %0, %1, %2;"
                            : "=l"(d) : "l"(b2[jp]), "l"(ad[i]));
                        d &= 0x7FFFFFFF7FFFFFFFULL;
                        asm("add.rn.f32x2 %0, %0, %1;"
                            : "+l"(acc2[i][jp]) : "l"(d));
                    }
                }
        }

        if (t + 1 < T) { storeA(buf ^ 1); storeB(buf ^ 1); }
        __syncthreads();
    }

    // ---- unpack ----
    float accf[TM][8];
#pragma unroll
    for (int i = 0; i < TM; i++)
#pragma unroll
        for (int jp = 0; jp < 4; jp++)
            asm("mov.b64 {%0, %1}, %2;"
                : "=f"(accf[i][2*jp]), "=f"(accf[i][2*jp+1]) : "l"(acc2[i][jp]));

    // ---- epilogue ----
#pragma unroll
    for (int i = 0; i < TM; i++) {
        int m = m0 + ty * TM + i;
        float inv = 1.0f, bias = 0.0f;
        if (EPI >= 1) {
            inv  = bg[m] * rsqrtf(bv[m] + 1e-5f);
            bias = bb[m] - bm[m] * inv;
        }
        if (EPI == 2) {
#pragma unroll
            for (int j = 0; j < 8; j++) {
                int n   = n0 + tx * 8 + j;
                int b_  = n / HWSZ;
                int hw  = n - b_ * HWSZ;
                int idx = (b_ * 512 + m) * HWSZ + hw;
                float v = -accf[i][j];
                v = v * inv + bias + resid[idx];
                Y[idx] = fmaxf(v, 0.0f);
            }
        } else {
            float o[8];
#pragma unroll
            for (int j = 0; j < 8; j++) {
                float v = (MODE == 0) ? accf[i][j] : -accf[i][j];
                if (EPI == 1) v = fmaxf(v * inv + bias, 0.0f);
                o[j] = v;
            }
            int base = m * NTOT + n0 + tx * 8;
            *(float4*)&Y[base]     = make_float4(o[0], o[1], o[2], o[3]);
            *(float4*)&Y[base + 4] = make_float4(o[4], o[5], o[6], o[7]);
        }
    }
}

// ---------------------------------------------------------------------------
extern "C" void kernel_launch(void* const* d_in, const int* in_sizes, int n_in,
                              void* d_out, int out_size) {
    const float* x   = (const float*)d_in[0];
    const float* w1s = (const float*)d_in[1];
    const float* w1a = (const float*)d_in[2];
    const float* w2s = (const float*)d_in[3];
    const float* w2a = (const float*)d_in[4];
    const float* w3s = (const float*)d_in[5];
    const float* w3a = (const float*)d_in[6];
    const float* g1 = (const float*)d_in[7],  *b1 = (const float*)d_in[8];
    const float* m1 = (const float*)d_in[9],  *v1 = (const float*)d_in[10];
    const float* g2 = (const float*)d_in[11], *b2 = (const float*)d_in[12];
    const float* m2 = (const float*)d_in[13], *v2 = (const float*)d_in[14];
    const float* g3 = (const float*)d_in[15], *b3 = (const float*)d_in[16];
    const float* m3 = (const float*)d_in[17], *v3 = (const float*)d_in[18];
    float* out = (float*)d_out;

    wprep_all<<<(704512 + 255) / 256, 256>>>(w1s, w1a, w2s, w2a, w3s, w3a);
    transpose_x<<<(512 * (NTOT / 4) + 255) / 256, 256>>>(x);

    // stage 1 (M=128 -> BM=32, 392 blocks)
    gx<32,2,16, 0,0,0, 4,0,1><<<dim3(98,4), 256>>>(
        nullptr, 128, 512, nullptr, nullptr, nullptr, nullptr, nullptr);
    gx<32,2,16, 1,0,1, 5,1,2><<<dim3(98,4), 256>>>(
        nullptr, 128, 128, g1, b1, m1, v1, nullptr);

    // stage 2 (3x3, K=1152, BK=18, M=128 -> BM=32)
    gx<32,2,18, 0,1,0, 6,2,3><<<dim3(98,4), 256>>>(
        nullptr, 128, 1152, nullptr, nullptr, nullptr, nullptr, nullptr);
    gx<32,2,18, 1,1,1, 7,3,2><<<dim3(98,4), 256>>>(
        nullptr, 128, 1152, g2, b2, m2, v2, nullptr);

    // stage 3 (M=512 -> BM=64, 784 blocks)
    gx<64,4,16, 0,0,0, 8,2,1><<<dim3(98,8), 256>>>(
        nullptr, 512, 128, nullptr, nullptr, nullptr, nullptr, nullptr);
    gx<64,4,16, 1,0,2, 9,1,-1><<<dim3(98,8), 256>>>(
        out, 512, 512, g3, b3, m3, v3, x);
}

// round 5
// speedup vs baseline: 1.3049x; 1.3049x over previous
#include <cuda_runtime.h>

#define NTOT 12544   // 16 * 784 flattened spatial*batch
#define HWSZ 784
#define WD   28

// ---------------- scratch (device globals; no allocation allowed) ----------
__device__ float g_xT  [512 * NTOT];   // x transposed to [c][n]
__device__ float g_A   [512 * NTOT];   // t1 (128 rows) then t3 (512 rows)
__device__ float g_B   [128 * NTOT];   // u1 then u2
__device__ float g_C   [128 * NTOT];   // t2
__device__ float g_q1T [512 * 128];    // quantized w1s, k-major [c][p]
__device__ float g_w1aT[128 * 128];    // w1a k-major, NEGATED
__device__ float g_q2T [1152 * 128];
__device__ float g_w2aT[1152 * 128];   // negated
__device__ float g_q3T [128 * 512];
__device__ float g_w3aT[512 * 512];    // negated

template<int ID>
__device__ __forceinline__ float* gbuf(float* rt) {
    if constexpr (ID == 0) return g_xT;
    else if constexpr (ID == 1) return g_A;
    else if constexpr (ID == 2) return g_B;
    else if constexpr (ID == 3) return g_C;
    else if constexpr (ID == 4) return g_q1T;
    else if constexpr (ID == 5) return g_w1aT;
    else if constexpr (ID == 6) return g_q2T;
    else if constexpr (ID == 7) return g_w2aT;
    else if constexpr (ID == 8) return g_q3T;
    else if constexpr (ID == 9) return g_w3aT;
    else return rt;
}

// ---- one kernel for all weight prep (quantize/negate + k-major transpose) -
__device__ __forceinline__ void wp_one(const float* src, float* dst,
                                       int i, int M, int K, int quant, int neg) {
    int m = i / K, k = i - m * K;
    float w = src[i];
    float q = w;
    if (quant) {
        float a = fabsf(w) + 1e-8f;
        q = copysignf(exp2f(rintf(log2f(a))), w);
        if (w == 0.0f) q = 0.0f;   // jnp.sign(0) == 0
    }
    if (neg) q = -q;
    dst[k * M + m] = q;
}

__global__ void wprep_all(const float* __restrict__ w1s, const float* __restrict__ w1a,
                          const float* __restrict__ w2s, const float* __restrict__ w2a,
                          const float* __restrict__ w3s, const float* __restrict__ w3a) {
    int gid = blockIdx.x * blockDim.x + threadIdx.x;
    if (gid < 65536)                 wp_one(w1s, g_q1T,  gid,          128, 512,  1, 0);
    else if (gid < 81920)            wp_one(w1a, g_w1aT, gid - 65536,  128, 128,  0, 1);
    else if (gid < 229376)           wp_one(w2s, g_q2T,  gid - 81920,  128, 1152, 1, 0);
    else if (gid < 376832)           wp_one(w2a, g_w2aT, gid - 229376, 128, 1152, 0, 1);
    else if (gid < 442368)           wp_one(w3s, g_q3T,  gid - 376832, 512, 128,  1, 0);
    else if (gid < 704512)           wp_one(w3a, g_w3aT, gid - 442368, 512, 512,  0, 1);
}

// -------- x: NCHW -> [c][b*784+hw] ----------------------------------------
__global__ void transpose_x(const float* __restrict__ x) {
    int i = blockIdx.x * blockDim.x + threadIdx.x;   // float4 index
    if (i >= 512 * (NTOT / 4)) return;
    int c  = i / (NTOT / 4);
    int r  = i - c * (NTOT / 4);
    int n  = r * 4;
    int b  = n / HWSZ;
    int hw = n - b * HWSZ;
    float4 v = ((const float4*)x)[((b * 512 + c) * HWSZ + hw) >> 2];
    ((float4*)g_xT)[i] = v;
}

// ---------------------------------------------------------------------------
// GEMM-shaped kernel. BN=128, NT=(BM/TM)*16 threads, TM x 8 thread tile,
// A tile duplicated in smem ([a,a,...]) -> LDS.128 gives ready {a,a} pairs,
// zero pack MOVs. Double-buffered smem, one sync per K-tile.
//   MODE 0: acc += a*b   MODE 1: acc += |b-a| (A negated; epilogue negates)
//   CONV 0: B = X[k][n]  CONV 1: implicit 3x3, zero halo (BK=18)
//   EPI 0: plain  EPI 1: relu(bn)  EPI 2: relu(bn+resid) NCHW store
// ---------------------------------------------------------------------------
template<int BM, int TM, int BK, int MODE, int CONV, int EPI,
         int WID, int XID, int YID>
__global__ void __launch_bounds__((BM/TM)*16)
gx(float* Yrt, int Mtot, int K,
   const float* __restrict__ bg, const float* __restrict__ bb,
   const float* __restrict__ bm, const float* __restrict__ bv,
   const float* __restrict__ resid)
{
    constexpr int BN = 128;
    constexpr int NT = (BM / TM) * 16;
    static_assert(CONV == 0 || NT == 128, "conv fill assumes 128 threads");
    constexpr int AF4 = BK * BM / 4;
    constexpr int AU  = (AF4 + NT - 1) / NT;
    constexpr int BU  = BK * BN / 4 / NT;
    const float* Wt = gbuf<WID>(nullptr);
    const float* X  = gbuf<XID>(nullptr);
    float*       Y  = gbuf<YID>(Yrt);

    __shared__ __align__(16) float As[2][BK * BM * 2];   // duplicated
    __shared__ __align__(16) float Bs[2][BK * BN];

    int tid = threadIdx.x;
    int tx  = tid % 16;            // 16 col groups of 8
    int ty  = tid / 16;            // row groups of TM
    int m0  = blockIdx.y * BM;
    int n0  = blockIdx.x * BN;

    // conv geometry: thread owns column tid; fills both channels of the BK=18 slab
    int cn = n0 + (tid & 127);
    int cw = cn % WD;
    int ch = (cn / WD) % WD;

    float4 pa[AU];
    float4 pb[BU > 0 ? BU : 1];
    float  pc[CONV ? 18 : 1];

    auto loadA = [&](int k0) {
#pragma unroll
        for (int u = 0; u < AU; u++) {
            int v = tid + u * NT;
            if (AF4 % NT == 0 || v < AF4) {
                int kk = v / (BM / 4), mq = v - kk * (BM / 4);
                pa[u] = *(const float4*)&Wt[(k0 + kk) * Mtot + m0 + mq * 4];
            }
        }
    };
    auto storeA = [&](int buf) {
#pragma unroll
        for (int u = 0; u < AU; u++) {
            int v = tid + u * NT;
            if (AF4 % NT == 0 || v < AF4) {
                int kk = v / (BM / 4), mq = v - kk * (BM / 4);
                float* d = &As[buf][kk * BM * 2 + mq * 8];
                *(float4*)(d)     = make_float4(pa[u].x, pa[u].x, pa[u].y, pa[u].y);
                *(float4*)(d + 4) = make_float4(pa[u].z, pa[u].z, pa[u].w, pa[u].w);
            }
        }
    };
    auto loadB = [&](int k0) {
        if (CONV == 0) {
#pragma unroll
            for (int u = 0; u < BU; u++) {
                int v = tid + u * NT;
                int kk = v / (BN / 4), nq = v - kk * (BN / 4);
                pb[u] = *(const float4*)&X[(k0 + kk) * NTOT + n0 + nq * 4];
            }
        } else {
            int c0 = k0 / 9;
#pragma unroll
            for (int half = 0; half < 2; half++)
#pragma unroll
                for (int q = 0; q < 9; q++) {
                    const int r = q / 3, s = q % 3;
                    int hh = ch + r - 1, ww = cw + s - 1;
                    float val = 0.0f;
                    if (hh >= 0 && hh < WD && ww >= 0 && ww < WD)
                        val = X[(c0 + half) * NTOT + cn + (r - 1) * WD + (s - 1)];
                    pc[half * 9 + q] = val;
                }
        }
    };
    auto storeB = [&](int buf) {
        if (CONV == 0) {
#pragma unroll
            for (int u = 0; u < BU; u++) {
                int v = tid + u * NT;
                int kk = v / (BN / 4), nq = v - kk * (BN / 4);
                *(float4*)&Bs[buf][kk * BN + nq * 4] = pb[u];
            }
        } else {
#pragma unroll
            for (int half = 0; half < 2; half++)
#pragma unroll
                for (int q = 0; q < 9; q++)
                    Bs[buf][(half * 9 + q) * BN + (tid & 127)] = pc[half * 9 + q];
        }
    };

    unsigned long long acc2[TM][4];
#pragma unroll
    for (int i = 0; i < TM; i++)
#pragma unroll
        for (int j = 0; j < 4; j++) acc2[i][j] = 0ULL;

    loadA(0); loadB(0);
    storeA(0); storeB(0);
    __syncthreads();

    int T = K / BK;
    for (int t = 0; t < T; t++) {
        int buf = t & 1;
        if (t + 1 < T) { loadA((t + 1) * BK); loadB((t + 1) * BK); }

#pragma unroll
        for (int kk = 0; kk < BK; kk++) {
            unsigned long long ad[TM];
#pragma unroll
            for (int h = 0; h < TM / 2; h++) {
                ulonglong2 p = *(const ulonglong2*)
                    &As[buf][kk * BM * 2 + ty * TM * 2 + h * 4];
                ad[2 * h] = p.x; ad[2 * h + 1] = p.y;
            }
            unsigned long long b2[4];
            {
                ulonglong2 p0 = *(const ulonglong2*)&Bs[buf][kk * BN + tx * 8];
                ulonglong2 p1 = *(const ulonglong2*)&Bs[buf][kk * BN + tx * 8 + 4];
                b2[0] = p0.x; b2[1] = p0.y; b2[2] = p1.x; b2[3] = p1.y;
            }
#pragma unroll
            for (int i = 0; i < TM; i++)
#pragma unroll
                for (int jp = 0; jp < 4; jp++) {
                    if (MODE == 0) {
                        asm("fma.rn.f32x2 %0, %1, %2, %0;"
                            : "+l"(acc2[i][jp]) : "l"(ad[i]), "l"(b2[jp]));
                    } else {
                        unsigned long long d;
                        asm("add.rn.f32x2 %0, %1, %2;"
                            : "=l"(d) : "l"(b2[jp]), "l"(ad[i]));
                        d &= 0x7FFFFFFF7FFFFFFFULL;
                        asm("add.rn.f32x2 %0, %0, %1;"
                            : "+l"(acc2[i][jp]) : "l"(d));
                    }
                }
        }

        if (t + 1 < T) { storeA(buf ^ 1); storeB(buf ^ 1); }
        __syncthreads();
    }

    // ---- unpack ----
    float accf[TM][8];
#pragma unroll
    for (int i = 0; i < TM; i++)
#pragma unroll
        for (int jp = 0; jp < 4; jp++)
            asm("mov.b64 {%0, %1}, %2;"
                : "=f"(accf[i][2*jp]), "=f"(accf[i][2*jp+1]) : "l"(acc2[i][jp]));

    // ---- epilogue ----
#pragma unroll
    for (int i = 0; i < TM; i++) {
        int m = m0 + ty * TM + i;
        float inv = 1.0f, bias = 0.0f;
        if (EPI >= 1) {
            inv  = bg[m] * rsqrtf(bv[m] + 1e-5f);
            bias = bb[m] - bm[m] * inv;
        }
        if (EPI == 2) {
#pragma unroll
            for (int j = 0; j < 8; j++) {
                int n   = n0 + tx * 8 + j;
                int b_  = n / HWSZ;
                int hw  = n - b_ * HWSZ;
                int idx = (b_ * 512 + m) * HWSZ + hw;
                float v = -accf[i][j];
                v = v * inv + bias + resid[idx];
                Y[idx] = fmaxf(v, 0.0f);
            }
        } else {
            float o[8];
#pragma unroll
            for (int j = 0; j < 8; j++) {
                float v = (MODE == 0) ? accf[i][j] : -accf[i][j];
                if (EPI == 1) v = fmaxf(v * inv + bias, 0.0f);
                o[j] = v;
            }
            int base = m * NTOT + n0 + tx * 8;
            *(float4*)&Y[base]     = make_float4(o[0], o[1], o[2], o[3]);
            *(float4*)&Y[base + 4] = make_float4(o[4], o[5], o[6], o[7]);
        }
    }
}

// ---------------------------------------------------------------------------
extern "C" void kernel_launch(void* const* d_in, const int* in_sizes, int n_in,
                              void* d_out, int out_size) {
    const float* x   = (const float*)d_in[0];
    const float* w1s = (const float*)d_in[1];
    const float* w1a = (const float*)d_in[2];
    const float* w2s = (const float*)d_in[3];
    const float* w2a = (const float*)d_in[4];
    const float* w3s = (const float*)d_in[5];
    const float* w3a = (const float*)d_in[6];
    const float* g1 = (const float*)d_in[7],  *b1 = (const float*)d_in[8];
    const float* m1 = (const float*)d_in[9],  *v1 = (const float*)d_in[10];
    const float* g2 = (const float*)d_in[11], *b2 = (const float*)d_in[12];
    const float* m2 = (const float*)d_in[13], *v2 = (const float*)d_in[14];
    const float* g3 = (const float*)d_in[15], *b3 = (const float*)d_in[16];
    const float* m3 = (const float*)d_in[17], *v3 = (const float*)d_in[18];
    float* out = (float*)d_out;

    wprep_all<<<(704512 + 255) / 256, 256>>>(w1s, w1a, w2s, w2a, w3s, w3a);
    transpose_x<<<(512 * (NTOT / 4) + 255) / 256, 256>>>(x);

    // stage 1 (M=128): BM=32, TM=4, 128 threads, 392 blocks
    gx<32,4,16, 0,0,0, 4,0,1><<<dim3(98,4), 128>>>(
        nullptr, 128, 512, nullptr, nullptr, nullptr, nullptr, nullptr);
    gx<32,4,16, 1,0,1, 5,1,2><<<dim3(98,4), 128>>>(
        nullptr, 128, 128, g1, b1, m1, v1, nullptr);

    // stage 2 (3x3, K=1152, BK=18): BM=32, TM=4
    gx<32,4,18, 0,1,0, 6,2,3><<<dim3(98,4), 128>>>(
        nullptr, 128, 1152, nullptr, nullptr, nullptr, nullptr, nullptr);
    gx<32,4,18, 1,1,1, 7,3,2><<<dim3(98,4), 128>>>(
        nullptr, 128, 1152, g2, b2, m2, v2, nullptr);

    // stage 3 (M=512): BM=64, TM=8, 128 threads, 784 blocks
    gx<64,8,16, 0,0,0, 8,2,1><<<dim3(98,8), 128>>>(
        nullptr, 512, 128, nullptr, nullptr, nullptr, nullptr, nullptr);
    gx<64,8,16, 1,0,2, 9,1,-1><<<dim3(98,8), 128>>>(
        out, 512, 512, g3, b3, m3, v3, x);
}